// round 7
// baseline (speedup 1.0000x reference)
#include <cuda_runtime.h>
#include <cstdint>
#include <math.h>

// ---------------- problem constants ----------------
#define HD     1024
#define FOURH  4096
#define BATCH  2048
#define SEQ    24
#define EDIM   256
#define VOCAB  37
#define MROWS  (BATCH*SEQ)   // 49152

// ---------------- device scratch (no allocation allowed) ----------------
__device__ float g_Xg[(size_t)MROWS * FOURH];     // 805 MB : per-layer input projections
__device__ float g_gates[(size_t)BATCH * FOURH];  // 33.5 MB: per-step gate scratch
__device__ float g_y[(size_t)MROWS * HD];         // 201 MB : per-layer outputs
__device__ float g_state[(size_t)4 * BATCH * HD]; // h0,c0,h1,c1
__device__ int   g_dectok[BATCH * SEQ];

// ---------------- small helpers ----------------
__device__ __forceinline__ uint32_t f2tf(float x) {
    uint32_t r;
    asm("cvt.rna.tf32.f32 %0, %1;" : "=r"(r) : "f"(x));
    return r;
}

__device__ __forceinline__ void mma_tf32(float* c, const uint32_t* a, const uint32_t* b) {
    asm volatile(
        "mma.sync.aligned.m16n8k8.row.col.f32.tf32.tf32.f32 "
        "{%0,%1,%2,%3}, {%4,%5,%6,%7}, {%8,%9}, {%0,%1,%2,%3};\n"
        : "+f"(c[0]), "+f"(c[1]), "+f"(c[2]), "+f"(c[3])
        : "r"(a[0]), "r"(a[1]), "r"(a[2]), "r"(a[3]), "r"(b[0]), "r"(b[1]));
}

__device__ __forceinline__ void cp16(void* s, const void* g) {
    uint32_t sa = (uint32_t)__cvta_generic_to_shared(s);
    asm volatile("cp.async.ca.shared.global [%0], [%1], 16;\n" :: "r"(sa), "l"(g));
}
#define CP_COMMIT() asm volatile("cp.async.commit_group;\n" ::)
#define CP_WAIT(n)  asm volatile("cp.async.wait_group %0;\n" :: "n"(n))

// ---------------- GEMM: C[M,4096] = A[M,K] @ W[4096,K]^T (+ epilogue) ----------------
// MODE 0: input projection.  A row m = (tok ? emb[tok[m]] : A[m]).  C = acc + bias1 + bias2.
// MODE 1: recurrent step.    A = h.  C(gates) = acc + Xg[(m*SEQ + t)*4096 + n].
constexpr int BM = 128, BN = 128, BK = 16, SPAD = 4;  // smem stride 20 floats -> conflict-free

template<int MODE>
__global__ __launch_bounds__(128)
void gemm_tf32(const float* __restrict__ A, const int* __restrict__ tok,
               const float* __restrict__ W,
               const float* __restrict__ bias1, const float* __restrict__ bias2,
               const float* __restrict__ addXg, float* __restrict__ C,
               int K, int t)
{
    __shared__ float sA[2][BM][BK + SPAD];
    __shared__ float sB[2][BN][BK + SPAD];

    const int tid  = threadIdx.x;
    const int bm   = blockIdx.y * BM;
    const int bn   = blockIdx.x * BN;
    const int ldr  = tid >> 2;          // 0..31
    const int ldc  = (tid & 3) * 4;     // 0,4,8,12

    // loader base pointers (token gather folded in)
    const float* abase[4];
    const float* bbase[4];
#pragma unroll
    for (int i = 0; i < 4; ++i) {
        int m = bm + ldr + i * 32;
        const float* base = tok ? (A + (size_t)tok[m] * K) : (A + (size_t)m * K);
        abase[i] = base + ldc;
        bbase[i] = W + (size_t)(bn + ldr + i * 32) * K + ldc;
    }

    const int KT = K / BK;

    // prologue: stage 0 and 1
#pragma unroll
    for (int i = 0; i < 4; ++i) cp16(&sA[0][ldr + i * 32][ldc], abase[i]);
#pragma unroll
    for (int i = 0; i < 4; ++i) cp16(&sB[0][ldr + i * 32][ldc], bbase[i]);
    CP_COMMIT();
#pragma unroll
    for (int i = 0; i < 4; ++i) cp16(&sA[1][ldr + i * 32][ldc], abase[i] + BK);
#pragma unroll
    for (int i = 0; i < 4; ++i) cp16(&sB[1][ldr + i * 32][ldc], bbase[i] + BK);
    CP_COMMIT();
    CP_WAIT(1);
    __syncthreads();

    const int wid  = tid >> 5;
    const int lane = tid & 31;
    const int wm   = (wid >> 1) * 64;   // warp M offset
    const int wn   = (wid & 1) * 64;    // warp N offset
    const int lr   = lane >> 2;         // 0..7
    const int lc   = lane & 3;          // 0..3

    float acc[4][8][4];
#pragma unroll
    for (int a = 0; a < 4; ++a)
#pragma unroll
        for (int b = 0; b < 8; ++b)
#pragma unroll
            for (int q = 0; q < 4; ++q) acc[a][b][q] = 0.f;

    for (int kt = 0; kt < KT; ++kt) {
        const int buf = kt & 1;
#pragma unroll
        for (int ks = 0; ks < 2; ++ks) {
            const int k0 = ks * 8;
            uint32_t af[4][4], bf[8][2];
#pragma unroll
            for (int mt = 0; mt < 4; ++mt) {
                int r = wm + mt * 16 + lr;
                af[mt][0] = f2tf(sA[buf][r][k0 + lc]);
                af[mt][1] = f2tf(sA[buf][r + 8][k0 + lc]);
                af[mt][2] = f2tf(sA[buf][r][k0 + lc + 4]);
                af[mt][3] = f2tf(sA[buf][r + 8][k0 + lc + 4]);
            }
#pragma unroll
            for (int nt = 0; nt < 8; ++nt) {
                int n = wn + nt * 8 + lr;
                bf[nt][0] = f2tf(sB[buf][n][k0 + lc]);
                bf[nt][1] = f2tf(sB[buf][n][k0 + lc + 4]);
            }
#pragma unroll
            for (int mt = 0; mt < 4; ++mt)
#pragma unroll
                for (int nt = 0; nt < 8; ++nt)
                    mma_tf32(acc[mt][nt], af[mt], bf[nt]);
        }
        __syncthreads();                 // everyone done reading buf
        if (kt + 2 < KT) {
#pragma unroll
            for (int i = 0; i < 4; ++i) cp16(&sA[buf][ldr + i * 32][ldc], abase[i] + (kt + 2) * BK);
#pragma unroll
            for (int i = 0; i < 4; ++i) cp16(&sB[buf][ldr + i * 32][ldc], bbase[i] + (kt + 2) * BK);
            CP_COMMIT();
        }
        if (kt + 1 < KT) {
            if (kt + 2 < KT) { CP_WAIT(1); } else { CP_WAIT(0); }
            __syncthreads();
        }
    }

    // epilogue
#pragma unroll
    for (int mt = 0; mt < 4; ++mt) {
        int gr0 = bm + wm + mt * 16 + lr;
        int gr1 = gr0 + 8;
#pragma unroll
        for (int nt = 0; nt < 8; ++nt) {
            int gc = bn + wn + nt * 8 + lc * 2;
            float2 v0, v1;
            if (MODE == 0) {
                float bx = bias1[gc] + bias2[gc];
                float by = bias1[gc + 1] + bias2[gc + 1];
                v0.x = acc[mt][nt][0] + bx; v0.y = acc[mt][nt][1] + by;
                v1.x = acc[mt][nt][2] + bx; v1.y = acc[mt][nt][3] + by;
            } else {
                float2 x0 = *(const float2*)&addXg[((size_t)gr0 * SEQ + t) * FOURH + gc];
                float2 x1 = *(const float2*)&addXg[((size_t)gr1 * SEQ + t) * FOURH + gc];
                v0.x = acc[mt][nt][0] + x0.x; v0.y = acc[mt][nt][1] + x0.y;
                v1.x = acc[mt][nt][2] + x1.x; v1.y = acc[mt][nt][3] + x1.y;
            }
            *(float2*)&C[(size_t)gr0 * FOURH + gc] = v0;
            *(float2*)&C[(size_t)gr1 * FOURH + gc] = v1;
        }
    }
}

// ---------------- LSTM pointwise cell ----------------
__device__ __forceinline__ float sigf(float x) { return 1.f / (1.f + expf(-x)); }

__global__ __launch_bounds__(256)
void lstm_cell_k(const float* __restrict__ gates, float* __restrict__ h,
                 float* __restrict__ c, float* __restrict__ y, int t, int writeY)
{
    int idx = blockIdx.x * 256 + threadIdx.x;      // over BATCH * HD/4
    int m = idx >> 8;
    int j = (idx & 255) << 2;
    size_t gb = (size_t)m * FOURH + j;
    float4 gi = *(const float4*)&gates[gb];
    float4 gf = *(const float4*)&gates[gb + 1024];
    float4 gg = *(const float4*)&gates[gb + 2048];
    float4 go = *(const float4*)&gates[gb + 3072];
    size_t cb = (size_t)m * HD + j;
    float4 cc = *(const float4*)&c[cb];
    float4 cn, hn;
    cn.x = sigf(gf.x) * cc.x + sigf(gi.x) * tanhf(gg.x); hn.x = sigf(go.x) * tanhf(cn.x);
    cn.y = sigf(gf.y) * cc.y + sigf(gi.y) * tanhf(gg.y); hn.y = sigf(go.y) * tanhf(cn.y);
    cn.z = sigf(gf.z) * cc.z + sigf(gi.z) * tanhf(gg.z); hn.z = sigf(go.z) * tanhf(cn.z);
    cn.w = sigf(gf.w) * cc.w + sigf(gi.w) * tanhf(gg.w); hn.w = sigf(go.w) * tanhf(cn.w);
    *(float4*)&c[cb] = cn;
    *(float4*)&h[cb] = hn;
    if (writeY) *(float4*)&y[((size_t)m * SEQ + t) * HD + j] = hn;
}

// ---------------- misc kernels ----------------
__global__ void zero_k(float* p, int n4)
{
    int i = blockIdx.x * blockDim.x + threadIdx.x;
    if (i < n4) ((float4*)p)[i] = make_float4(0.f, 0.f, 0.f, 0.f);
}

__global__ void build_dectok_k(const int* __restrict__ tgt, int* __restrict__ dt)
{
    int idx = blockIdx.x * blockDim.x + threadIdx.x;
    if (idx < BATCH * SEQ) {
        int b = idx / SEQ, t = idx - b * SEQ;
        dt[idx] = (t == 0) ? 1 : tgt[b * SEQ + t - 1];
    }
}

// ---------------- output projection: out[M,37] = y[M,1024] @ fcW[37,1024]^T + fcb ----------------
__global__ __launch_bounds__(256)
void proj_k(const float* __restrict__ y, const float* __restrict__ fcW,
            const float* __restrict__ fcb, float* __restrict__ out)
{
    __shared__ float ys[128][65];
    __shared__ float ws[40][65];
    const int tid = threadIdx.x;
    const int gm0 = blockIdx.x * 128;
    const int r0  = (tid >> 3) * 4;     // 0..124
    const int n0  = (tid & 7) * 5;      // 0..35

    float acc[4][5];
#pragma unroll
    for (int i = 0; i < 4; ++i)
#pragma unroll
        for (int j = 0; j < 5; ++j) acc[i][j] = 0.f;

    for (int kc = 0; kc < 16; ++kc) {
        __syncthreads();
        // y chunk: 128 rows x 64 cols
        for (int i = tid; i < 128 * 16; i += 256) {
            int r = i >> 4, c4 = (i & 15) * 4;
            float4 v = *(const float4*)&y[(size_t)(gm0 + r) * HD + kc * 64 + c4];
            ys[r][c4] = v.x; ys[r][c4 + 1] = v.y; ys[r][c4 + 2] = v.z; ys[r][c4 + 3] = v.w;
        }
        // w chunk: 40 rows (3 padded with 0) x 64 cols
        for (int i = tid; i < 40 * 64; i += 256) {
            int n = i >> 6, cc = i & 63;
            ws[n][cc] = (n < VOCAB) ? fcW[n * HD + kc * 64 + cc] : 0.f;
        }
        __syncthreads();
#pragma unroll 8
        for (int k = 0; k < 64; ++k) {
            float yv[4], wv[5];
#pragma unroll
            for (int i = 0; i < 4; ++i) yv[i] = ys[r0 + i][k];
#pragma unroll
            for (int j = 0; j < 5; ++j) wv[j] = ws[n0 + j][k];
#pragma unroll
            for (int i = 0; i < 4; ++i)
#pragma unroll
                for (int j = 0; j < 5; ++j) acc[i][j] += yv[i] * wv[j];
        }
    }
#pragma unroll
    for (int i = 0; i < 4; ++i)
#pragma unroll
        for (int j = 0; j < 5; ++j) {
            int n = n0 + j;
            if (n < VOCAB)
                out[(size_t)(gm0 + r0 + i) * VOCAB + n] = acc[i][j] + fcb[n];
        }
}

// ---------------- host driver ----------------
extern "C" void kernel_launch(void* const* d_in, const int* in_sizes, int n_in,
                              void* d_out, int out_size)
{
    const int*   src    = (const int*)d_in[0];
    const int*   tgt    = (const int*)d_in[1];
    const float* emb    = (const float*)d_in[2];
    const float* eW_ih0 = (const float*)d_in[3];
    const float* eW_hh0 = (const float*)d_in[4];
    const float* eb_ih0 = (const float*)d_in[5];
    const float* eb_hh0 = (const float*)d_in[6];
    const float* eW_ih1 = (const float*)d_in[7];
    const float* eW_hh1 = (const float*)d_in[8];
    const float* eb_ih1 = (const float*)d_in[9];
    const float* eb_hh1 = (const float*)d_in[10];
    const float* dW_ih0 = (const float*)d_in[11];
    const float* dW_hh0 = (const float*)d_in[12];
    const float* db_ih0 = (const float*)d_in[13];
    const float* db_hh0 = (const float*)d_in[14];
    const float* dW_ih1 = (const float*)d_in[15];
    const float* dW_hh1 = (const float*)d_in[16];
    const float* db_ih1 = (const float*)d_in[17];
    const float* db_hh1 = (const float*)d_in[18];
    const float* fcW    = (const float*)d_in[19];
    const float* fcb    = (const float*)d_in[20];
    float* out = (float*)d_out;

    float *Xg, *gates, *y, *state;
    int*   dectok;
    cudaGetSymbolAddress((void**)&Xg,     g_Xg);
    cudaGetSymbolAddress((void**)&gates,  g_gates);
    cudaGetSymbolAddress((void**)&y,      g_y);
    cudaGetSymbolAddress((void**)&state,  g_state);
    cudaGetSymbolAddress((void**)&dectok, g_dectok);

    float* h0 = state;
    float* c0 = state + (size_t)1 * BATCH * HD;
    float* h1 = state + (size_t)2 * BATCH * HD;
    float* c1 = state + (size_t)3 * BATCH * HD;

    // zero h/c state
    {
        int n4 = 4 * BATCH * HD / 4;
        zero_k<<<(n4 + 255) / 256, 256>>>(state, n4);
    }
    build_dectok_k<<<(BATCH * SEQ + 255) / 256, 256>>>(tgt, dectok);

    const dim3 gBig(FOURH / BN, MROWS / BM);   // (32, 384)
    const dim3 gRec(FOURH / BN, BATCH / BM);   // (32, 16)
    const int  cellBlocks = (BATCH * HD / 4) / 256;  // 2048

    // ===== encoder layer 0 =====
    gemm_tf32<0><<<gBig, 128>>>(emb, src, eW_ih0, eb_ih0, eb_hh0, nullptr, Xg, EDIM, 0);
    for (int t = 0; t < SEQ; ++t) {
        gemm_tf32<1><<<gRec, 128>>>(h0, nullptr, eW_hh0, nullptr, nullptr, Xg, gates, HD, t);
        lstm_cell_k<<<cellBlocks, 256>>>(gates, h0, c0, y, t, 1);
    }
    // ===== encoder layer 1 =====
    gemm_tf32<0><<<gBig, 128>>>(y, nullptr, eW_ih1, eb_ih1, eb_hh1, nullptr, Xg, HD, 0);
    for (int t = 0; t < SEQ; ++t) {
        gemm_tf32<1><<<gRec, 128>>>(h1, nullptr, eW_hh1, nullptr, nullptr, Xg, gates, HD, t);
        lstm_cell_k<<<cellBlocks, 256>>>(gates, h1, c1, y, t, 0);
    }
    // ===== decoder layer 0 (state continues from encoder finals) =====
    gemm_tf32<0><<<gBig, 128>>>(emb, dectok, dW_ih0, db_ih0, db_hh0, nullptr, Xg, EDIM, 0);
    for (int t = 0; t < SEQ; ++t) {
        gemm_tf32<1><<<gRec, 128>>>(h0, nullptr, dW_hh0, nullptr, nullptr, Xg, gates, HD, t);
        lstm_cell_k<<<cellBlocks, 256>>>(gates, h0, c0, y, t, 1);
    }
    // ===== decoder layer 1 =====
    gemm_tf32<0><<<gBig, 128>>>(y, nullptr, dW_ih1, db_ih1, db_hh1, nullptr, Xg, HD, 0);
    for (int t = 0; t < SEQ; ++t) {
        gemm_tf32<1><<<gRec, 128>>>(h1, nullptr, dW_hh1, nullptr, nullptr, Xg, gates, HD, t);
        lstm_cell_k<<<cellBlocks, 256>>>(gates, h1, c1, y, t, 1);
    }
    // ===== output projection =====
    proj_k<<<MROWS / 128, 256>>>(y, fcW, fcb, out);
}